// round 1
// baseline (speedup 1.0000x reference)
#include <cuda_runtime.h>
#include <math.h>

#define Bsz 2
#define Cch 64
#define Hh  256
#define Ww  1216
#define HWs (Hh*Ww)          // 311296
#define NS  20000
#define Kn  9
#define Dd  131
#define Dhh 65

// ---------------- scratch (device globals: allocation-free) ----------------
__device__ float g_d0[(size_t)Bsz*Cch*HWs];    // updated depth features
__device__ float g_r0[(size_t)Bsz*Cch*HWs];    // updated rgb features
__device__ float g_dfeat[(size_t)Bsz*Cch*NS];  // compact attn outputs (d)
__device__ float g_rfeat[(size_t)Bsz*Cch*NS];  // compact attn outputs (r)

// ---------------- conv 3x3 SAME, 64 in-ch per source, up to 2 sources -----
// Block: 32x8 threads. Tile: 8 rows x 32 cols x 64 oc. Each thread: 8 rows x 8 oc.
__global__ __launch_bounds__(256, 2) void conv3x3_kernel(
    const float* __restrict__ x0, const float* __restrict__ w0,
    const float* __restrict__ x1, const float* __restrict__ w1,
    const float* __restrict__ b0, const float* __restrict__ b1,
    float* __restrict__ y)
{
    __shared__ float s_in[8][10][34];    // [ic][row][col]  10.9KB
    __shared__ float s_w[64*72];         // [oc][ic(8)][tap(9)] 18.4KB

    const int tx  = threadIdx.x;               // 0..31 col
    const int ty  = threadIdx.y;               // 0..7  oc group
    const int tid = ty*32 + tx;
    const int w0col = blockIdx.x * 32;
    const int h0    = blockIdx.y * 8;
    const int b     = blockIdx.z;

    float acc[8][8];
#pragma unroll
    for (int r = 0; r < 8; r++)
#pragma unroll
        for (int j = 0; j < 8; j++) acc[r][j] = 0.f;

#pragma unroll 1
    for (int src = 0; src < 2; src++) {
        const float* xs = src ? x1 : x0;
        const float* ws = src ? w1 : w0;
        if (xs == nullptr) break;
        const float* xb = xs + (size_t)b * Cch * HWs;

#pragma unroll 1
        for (int icc = 0; icc < 64; icc += 8) {
            // ---- load input patch (8 ic, 10 rows, 34 cols), zero-padded ----
            for (int i = tid; i < 8*10*34; i += 256) {
                int ic  = i / 340;
                int rem = i % 340;
                int r   = rem / 34;
                int c   = rem % 34;
                int h   = h0 - 1 + r;
                int wc  = w0col - 1 + c;
                float v = 0.f;
                if ((unsigned)h < (unsigned)Hh && (unsigned)wc < (unsigned)Ww)
                    v = xb[(size_t)(icc + ic) * HWs + (size_t)h * Ww + wc];
                s_in[ic][r][c] = v;
            }
            // ---- load weights chunk: s_w[oc*72 + ic*9 + tap] (coalesced) ----
            for (int i = tid; i < 64*72; i += 256) {
                int oc = i / 72;
                int r  = i % 72;                 // r = ic*9 + tap
                s_w[i] = ws[(size_t)oc*576 + (size_t)icc*9 + r];
            }
            __syncthreads();

            // ---- compute ----
#pragma unroll
            for (int ic = 0; ic < 8; ic++) {
#pragma unroll
                for (int dx = 0; dx < 3; dx++) {
                    float xr[10];
#pragma unroll
                    for (int r = 0; r < 10; r++) xr[r] = s_in[ic][r][tx + dx];
#pragma unroll
                    for (int dy = 0; dy < 3; dy++) {
                        float wv[8];
#pragma unroll
                        for (int j = 0; j < 8; j++)
                            wv[j] = s_w[(ty*8 + j)*72 + ic*9 + dy*3 + dx];
#pragma unroll
                        for (int r = 0; r < 8; r++)
#pragma unroll
                            for (int j = 0; j < 8; j++)
                                acc[r][j] = fmaf(xr[r + dy], wv[j], acc[r][j]);
                    }
                }
            }
            __syncthreads();
        }
    }

    // ---- epilogue: bias (+second bias) + relu, coalesced stores ----
    const int wx = w0col + tx;
#pragma unroll
    for (int j = 0; j < 8; j++) {
        int oc = ty*8 + j;
        float bias = b0[oc] + (b1 ? b1[oc] : 0.f);
#pragma unroll
        for (int r = 0; r < 8; r++) {
            float v = acc[r][j] + bias;
            v = fmaxf(v, 0.f);
            y[(size_t)(b*Cch + oc) * HWs + (size_t)(h0 + r) * Ww + wx] = v;
        }
    }
}

// ---------------- point stage: gather + 2 MLPs + softmax + weighted sum ----
__global__ __launch_bounds__(128) void point_kernel(
    const int* __restrict__ pc, const int* __restrict__ nbrs,
    const float* __restrict__ disp,
    const float* __restrict__ d_w1, const float* __restrict__ d_b1,
    const float* __restrict__ d_w2, const float* __restrict__ d_b2,
    const float* __restrict__ r_w1, const float* __restrict__ r_b1,
    const float* __restrict__ r_w2, const float* __restrict__ r_b2,
    const float* __restrict__ d_bias, const float* __restrict__ r_bias)
{
    const int n  = blockIdx.x;
    const int b  = blockIdx.y;
    const int tid = threadIdx.x;

    __shared__ float s_ds[64], s_rs[64];
    __shared__ float s_dnn[64][9];
    __shared__ float s_feat[9][132];     // [k][d], d<131
    __shared__ float s_h[2][9][66];      // hidden
    __shared__ float s_logit[2][9];
    __shared__ float s_attn[2][9];
    __shared__ int   s_nb[9];
    __shared__ int   s_pidx;

    if (tid == 0) s_pidx = pc[(size_t)b*NS + n];
    if (tid < Kn) s_nb[tid] = nbrs[((size_t)b*NS + n)*Kn + tid];
    __syncthreads();

    const float* d0b = g_d0 + (size_t)b * Cch * HWs;
    const float* r0b = g_r0 + (size_t)b * Cch * HWs;
    const int pidx = s_pidx;

    if (tid < 64) {
        s_ds[tid] = d0b[(size_t)tid * HWs + pidx];
        s_rs[tid] = r0b[(size_t)tid * HWs + pidx];
    }
    for (int i = tid; i < 64*Kn; i += 128) {
        int c = i / Kn, k = i % Kn;
        s_dnn[c][k] = d0b[(size_t)c * HWs + s_nb[k]];
    }
    if (tid < 3*Kn) {
        int c3 = tid / Kn, k = tid % Kn;
        s_feat[k][128 + c3] = disp[(((size_t)b*3 + c3)*NS + n)*Kn + k];
    }
    __syncthreads();

    // feats (note: r-neighbors are gathered from d0f, faithful to source)
    for (int i = tid; i < 64*Kn; i += 128) {
        int c = i / Kn, k = i % Kn;
        float dn = s_dnn[c][k];
        s_feat[k][c]      = dn - s_ds[c];
        s_feat[k][64 + c] = dn - s_rs[c];
    }
    __syncthreads();

    // MLP layer 1: h[m][k][j] = leaky_relu(feat[k] . W1[:,j] + b1[j])
    for (int t = tid; t < 2*Kn*Dhh; t += 128) {
        int m = t / (Kn*Dhh);
        int local = t % (Kn*Dhh);
        int k = local / Dhh;
        int j = local % Dhh;
        const float* W1 = m ? r_w1 : d_w1;
        float a = (m ? r_b1 : d_b1)[j];
#pragma unroll 1
        for (int d = 0; d < Dd; d++)
            a = fmaf(s_feat[k][d], __ldg(&W1[d*Dhh + j]), a);
        a = (a > 0.f) ? a : 0.2f * a;
        s_h[m][k][j] = a;
    }
    __syncthreads();

    // MLP layer 2 -> logits
    if (tid < 2*Kn) {
        int m = tid / Kn, k = tid % Kn;
        const float* W2 = m ? r_w2 : d_w2;
        float a = (m ? r_b2 : d_b2)[0];
#pragma unroll 1
        for (int j = 0; j < Dhh; j++)
            a = fmaf(s_h[m][k][j], __ldg(&W2[j]), a);
        s_logit[m][k] = a;
    }
    __syncthreads();

    // softmax over k
    if (tid < 2) {
        int m = tid;
        float mx = s_logit[m][0];
#pragma unroll
        for (int k = 1; k < Kn; k++) mx = fmaxf(mx, s_logit[m][k]);
        float sum = 0.f;
        float e[Kn];
#pragma unroll
        for (int k = 0; k < Kn; k++) { e[k] = expf(s_logit[m][k] - mx); sum += e[k]; }
        float inv = 1.f / sum;
#pragma unroll
        for (int k = 0; k < Kn; k++) s_attn[m][k] = e[k] * inv;
    }
    __syncthreads();

    // weighted sum per channel -> compact buffers
    if (tid < 64) {
        int c = tid;
        float a = d_bias[c];
#pragma unroll
        for (int k = 0; k < Kn; k++) a = fmaf(s_attn[0][k], s_dnn[c][k], a);
        g_dfeat[((size_t)b*Cch + c)*NS + n] = a;
    } else {
        int c = tid - 64;
        float a = r_bias[c];
#pragma unroll
        for (int k = 0; k < Kn; k++) a = fmaf(s_attn[1][k], s_dnn[c][k], a);
        g_rfeat[((size_t)b*Cch + c)*NS + n] = a;
    }
}

// ---------------- scatter update (pc indices are unique -> race-free) ------
// channel 0: replaced; channels 1..63: added (faithful to source mask bug)
__global__ __launch_bounds__(128) void scatter_kernel(const int* __restrict__ pc)
{
    const int n = blockIdx.x;
    const int b = blockIdx.y;
    const int tid = threadIdx.x;
    const int idx = pc[(size_t)b*NS + n];

    if (tid < 64) {
        int c = tid;
        float v = g_dfeat[((size_t)b*Cch + c)*NS + n];
        size_t o = ((size_t)b*Cch + c)*HWs + idx;
        g_d0[o] = (c == 0) ? v : (g_d0[o] + v);
    } else {
        int c = tid - 64;
        float v = g_rfeat[((size_t)b*Cch + c)*NS + n];
        size_t o = ((size_t)b*Cch + c)*HWs + idx;
        g_r0[o] = (c == 0) ? v : (g_r0[o] + v);
    }
}

// ---------------------------------------------------------------------------
extern "C" void kernel_launch(void* const* d_in, const int* in_sizes, int n_in,
                              void* d_out, int out_size)
{
    const float* rgb    = (const float*)d_in[0];
    const float* sdepth = (const float*)d_in[1];
    const int*   pc     = (const int*)  d_in[2];
    const int*   nbrs   = (const int*)  d_in[3];
    const float* disp   = (const float*)d_in[4];
    const float* d_c0w  = (const float*)d_in[5];
    const float* d_c0b  = (const float*)d_in[6];
    const float* d_c1w  = (const float*)d_in[7];
    const float* d_c1b  = (const float*)d_in[8];
    const float* d_c2w  = (const float*)d_in[9];
    const float* d_c2b  = (const float*)d_in[10];
    const float* r_c0w  = (const float*)d_in[11];
    const float* r_c0b  = (const float*)d_in[12];
    const float* r_c1w  = (const float*)d_in[13];
    const float* r_c1b  = (const float*)d_in[14];
    const float* r_c2w  = (const float*)d_in[15];
    const float* r_c2b  = (const float*)d_in[16];
    const float* d_w1   = (const float*)d_in[17];
    const float* d_b1   = (const float*)d_in[18];
    const float* d_w2   = (const float*)d_in[19];
    const float* d_b2   = (const float*)d_in[20];
    const float* r_w1   = (const float*)d_in[21];
    const float* r_b1   = (const float*)d_in[22];
    const float* r_w2   = (const float*)d_in[23];
    const float* r_b2   = (const float*)d_in[24];
    const float* d_bias = (const float*)d_in[25];
    const float* r_bias = (const float*)d_in[26];
    float* out = (float*)d_out;

    float *p_gd0, *p_gr0;
    cudaGetSymbolAddress((void**)&p_gd0, g_d0);
    cudaGetSymbolAddress((void**)&p_gr0, g_r0);

    dim3 cgrid(Ww/32, Hh/8, Bsz);
    dim3 cblk(32, 8);

    // Stage A: d0 = relu(conv(sdepth, w0d)), r0 = relu(conv(rgb, w0r))
    conv3x3_kernel<<<cgrid, cblk>>>(sdepth, d_c0w, nullptr, nullptr, d_c0b, nullptr, p_gd0);
    conv3x3_kernel<<<cgrid, cblk>>>(rgb,    r_c0w, nullptr, nullptr, r_c0b, nullptr, p_gr0);

    // Stage B: per-point gather + attention
    point_kernel<<<dim3(NS, Bsz), 128>>>(pc, nbrs, disp,
                                         d_w1, d_b1, d_w2, d_b2,
                                         r_w1, r_b1, r_w2, r_b2,
                                         d_bias, r_bias);
    scatter_kernel<<<dim3(NS, Bsz), 128>>>(pc);

    // Stage C (fused): out_d = relu(conv(d0', w2d) + conv(sdepth, w1d) + b2d + b1d)
    conv3x3_kernel<<<cgrid, cblk>>>(p_gd0, d_c2w, sdepth, d_c1w, d_c2b, d_c1b, out);
    conv3x3_kernel<<<cgrid, cblk>>>(p_gr0, r_c2w, rgb,    r_c1w, r_c2b, r_c1b,
                                    out + (size_t)Bsz*Cch*HWs);
}

// round 2
// speedup vs baseline: 1.7973x; 1.7973x over previous
#include <cuda_runtime.h>
#include <cuda_bf16.h>
#include <math.h>
#include <stdint.h>

#define Bsz 2
#define Cch 64
#define Hh  256
#define Ww  1216
#define HWs (Hh*Ww)          // 311296
#define NS  20000
#define Kn  9
#define Dd  131
#define Dhh 65
#define ICP 16               // halves per (row,col) cell in A smem

// ---------------- scratch (device globals: allocation-free) ----------------
__device__ float g_d0[(size_t)Bsz*Cch*HWs];    // updated depth features
__device__ float g_r0[(size_t)Bsz*Cch*HWs];    // updated rgb features
__device__ float g_dfeat[(size_t)Bsz*Cch*NS];  // compact attn outputs (d)
__device__ float g_rfeat[(size_t)Bsz*Cch*NS];  // compact attn outputs (r)
// packed weight fragments: 6 sets x [part2][chunk4][tap9][nf8][lane32][pair2]
#define WSET_U32 36864                          // 2*4*9*8*32*2
__device__ uint32_t g_wfrag[6*WSET_U32];

// ---------------- helpers ---------------------------------------------------
__device__ __forceinline__ uint32_t pack_bf2(float a, float b) {
    __nv_bfloat162 t;
    t.x = __float2bfloat16(a);
    t.y = __float2bfloat16(b);
    return *reinterpret_cast<uint32_t*>(&t);
}

__device__ __forceinline__ void mma_bf16(float c[4], const uint32_t a[4],
                                         uint32_t b0, uint32_t b1) {
    asm volatile(
        "mma.sync.aligned.m16n8k16.row.col.f32.bf16.bf16.f32 "
        "{%0,%1,%2,%3}, {%4,%5,%6,%7}, {%8,%9}, {%0,%1,%2,%3};"
        : "+f"(c[0]), "+f"(c[1]), "+f"(c[2]), "+f"(c[3])
        : "r"(a[0]), "r"(a[1]), "r"(a[2]), "r"(a[3]), "r"(b0), "r"(b1));
}

__device__ __forceinline__ void ldsm4(uint32_t a[4], uint32_t addr) {
    asm volatile("ldmatrix.sync.aligned.m8n8.x4.shared.b16 {%0,%1,%2,%3}, [%4];"
                 : "=r"(a[0]), "=r"(a[1]), "=r"(a[2]), "=r"(a[3]) : "r"(addr));
}

// ---------------- weight prepack: fp32 OIHW -> bf16 hi/lo mma fragments ----
// grid (288, 6), block 32.  288 = chunk4 * tap9 * nf8
__global__ void prepack_w(const float* __restrict__ w0, const float* __restrict__ w1,
                          const float* __restrict__ w2, const float* __restrict__ w3,
                          const float* __restrict__ w4, const float* __restrict__ w5)
{
    const float* w;
    switch (blockIdx.y) {
        case 0: w = w0; break; case 1: w = w1; break; case 2: w = w2; break;
        case 3: w = w3; break; case 4: w = w4; break; default: w = w5; break;
    }
    uint32_t* dst = g_wfrag + blockIdx.y * WSET_U32;

    int cb = blockIdx.x;
    int chunk = cb / 72;
    int rem = cb % 72;
    int tap = rem / 8;
    int nf = rem % 8;
    int lane = threadIdx.x;

    int oc = nf*8 + (lane >> 2);
    int k0 = (lane & 3) * 2;
    int ic = chunk*16 + k0;

    float v00 = w[oc*576 + ic*9 + tap];
    float v01 = w[oc*576 + (ic+1)*9 + tap];
    float v10 = w[oc*576 + (ic+8)*9 + tap];
    float v11 = w[oc*576 + (ic+9)*9 + tap];

    float h00 = __bfloat162float(__float2bfloat16(v00));
    float h01 = __bfloat162float(__float2bfloat16(v01));
    float h10 = __bfloat162float(__float2bfloat16(v10));
    float h11 = __bfloat162float(__float2bfloat16(v11));

    // hi part (p=0)
    size_t base0 = ((((size_t)0*4 + chunk)*9 + tap)*8 + nf)*64 + lane*2;
    dst[base0 + 0] = pack_bf2(h00, h01);
    dst[base0 + 1] = pack_bf2(h10, h11);
    // lo part (p=1)
    size_t base1 = ((((size_t)1*4 + chunk)*9 + tap)*8 + nf)*64 + lane*2;
    dst[base1 + 0] = pack_bf2(v00 - h00, v01 - h01);
    dst[base1 + 1] = pack_bf2(v10 - h10, v11 - h11);
}

// ---------------- conv 3x3 SAME via mma (split bf16), up to 2 sources ------
// Block 256 thr (8 warps). Tile: 8 rows x 16 cols x 64 oc. Warp = 1 image row.
__global__ __launch_bounds__(256) void conv3x3_mma(
    const float* __restrict__ x0, const uint32_t* __restrict__ wf0,
    const float* __restrict__ x1, const uint32_t* __restrict__ wf1,
    const float* __restrict__ b0, const float* __restrict__ b1,
    float* __restrict__ y)
{
    __shared__ __align__(16) unsigned char sraw[48384];
    __nv_bfloat16* s_ah = (__nv_bfloat16*)sraw;             // 2880 halves = 5760B
    __nv_bfloat16* s_al = (__nv_bfloat16*)(sraw + 5760);    // 5760B
    uint32_t*      s_bf = (uint32_t*)(sraw + 11520);        // 9216 u32 = 36864B
    float*         s_out = (float*)sraw;                    // alias, 128*66*4B

    const int tid  = threadIdx.x;
    const int lane = tid & 31;
    const int wid  = tid >> 5;          // image row within tile
    const int w0c  = blockIdx.x * 16;
    const int h0   = blockIdx.y * 8;
    const int b    = blockIdx.z;

    float c[8][4];
#pragma unroll
    for (int nf = 0; nf < 8; nf++)
#pragma unroll
        for (int j = 0; j < 4; j++) c[nf][j] = 0.f;

    const int mm   = lane & 15;              // A row (= tile col)
    const int kofs = (lane >> 4) << 3;       // 0 or 8

    uint32_t a_hi_base = (uint32_t)__cvta_generic_to_shared(s_ah);
    uint32_t a_lo_base = (uint32_t)__cvta_generic_to_shared(s_al);

#pragma unroll 1
    for (int src = 0; src < 2; src++) {
        const float* xs = src ? x1 : x0;
        const uint32_t* wf = src ? wf1 : wf0;
        if (xs == nullptr) break;
        const float* xb = xs + (size_t)b * Cch * HWs;

#pragma unroll 1
        for (int cc = 0; cc < 4; cc++) {
            __syncthreads();
            // ---- load + split A halo tile: 16 ic x 10 rows x 18 cols ----
            for (int i = tid; i < 2880; i += 256) {
                int ic   = i / 180;
                int rem  = i % 180;
                int rowh = rem / 18;
                int col  = rem % 18;
                int h  = h0 - 1 + rowh;
                int wc = w0c - 1 + col;
                float v = 0.f;
                if ((unsigned)h < (unsigned)Hh && (unsigned)wc < (unsigned)Ww)
                    v = xb[(size_t)(cc*16 + ic) * HWs + (size_t)h * Ww + wc];
                __nv_bfloat16 hi = __float2bfloat16(v);
                float lo = v - __bfloat162float(hi);
                int si = (rowh*18 + col)*ICP + ic;
                s_ah[si] = hi;
                s_al[si] = __float2bfloat16(lo);
            }
            // ---- load B fragments for this chunk (hi and lo parts) ----
            for (int i = tid; i < 9216; i += 256) {
                int p = i / 4608;
                int j = i - p*4608;
                s_bf[i] = wf[(size_t)(p*4 + cc)*4608 + j];
            }
            __syncthreads();

            // ---- compute: 9 taps x 8 nfrags x 3 split products ----
#pragma unroll
            for (int tap = 0; tap < 9; tap++) {
                const int dy = tap / 3, dx = tap % 3;
                uint32_t aidx = (uint32_t)((((wid + dy)*18) + (mm + dx))*ICP + kofs) * 2u;
                uint32_t ah[4], al[4];
                ldsm4(ah, a_hi_base + aidx);
                ldsm4(al, a_lo_base + aidx);
#pragma unroll
                for (int nf = 0; nf < 8; nf++) {
                    uint2 bh = *(const uint2*)&s_bf[(tap*8 + nf)*64 + lane*2];
                    uint2 bl = *(const uint2*)&s_bf[((9 + tap)*8 + nf)*64 + lane*2];
                    mma_bf16(c[nf], ah, bh.x, bh.y);
                    mma_bf16(c[nf], ah, bl.x, bl.y);
                    mma_bf16(c[nf], al, bh.x, bh.y);
                }
            }
        }
    }
    __syncthreads();

    // ---- epilogue: frags -> smem transpose ----
    {
        int pix0 = wid*16 + (lane >> 2);
        int oc0  = (lane & 3) * 2;
#pragma unroll
        for (int nf = 0; nf < 8; nf++) {
            int oc = nf*8 + oc0;
            s_out[pix0*66 + oc]       = c[nf][0];
            s_out[pix0*66 + oc + 1]   = c[nf][1];
            s_out[(pix0+8)*66 + oc]     = c[nf][2];
            s_out[(pix0+8)*66 + oc + 1] = c[nf][3];
        }
    }
    __syncthreads();

    // ---- bias + relu + coalesced NCHW store ----
    for (int i = tid; i < 8192; i += 256) {
        int oc = i >> 7;
        int pix = i & 127;
        float bias = b0[oc] + (b1 ? b1[oc] : 0.f);
        float v = s_out[pix*66 + oc] + bias;
        v = fmaxf(v, 0.f);
        y[((size_t)(b*Cch + oc))*HWs + (size_t)(h0 + (pix >> 4))*Ww + (w0c + (pix & 15))] = v;
    }
}

// ---------------- point stage: gather + 2 MLPs + softmax + weighted sum ----
__global__ __launch_bounds__(128) void point_kernel(
    const int* __restrict__ pc, const int* __restrict__ nbrs,
    const float* __restrict__ disp,
    const float* __restrict__ d_w1, const float* __restrict__ d_b1,
    const float* __restrict__ d_w2, const float* __restrict__ d_b2,
    const float* __restrict__ r_w1, const float* __restrict__ r_b1,
    const float* __restrict__ r_w2, const float* __restrict__ r_b2,
    const float* __restrict__ d_bias, const float* __restrict__ r_bias)
{
    const int n  = blockIdx.x;
    const int b  = blockIdx.y;
    const int tid = threadIdx.x;

    __shared__ float s_ds[64], s_rs[64];
    __shared__ float s_dnn[64][9];
    __shared__ float s_feat[9][132];
    __shared__ float s_h[2][9][66];
    __shared__ float s_logit[2][9];
    __shared__ float s_attn[2][9];
    __shared__ int   s_nb[9];
    __shared__ int   s_pidx;

    if (tid == 0) s_pidx = pc[(size_t)b*NS + n];
    if (tid < Kn) s_nb[tid] = nbrs[((size_t)b*NS + n)*Kn + tid];
    __syncthreads();

    const float* d0b = g_d0 + (size_t)b * Cch * HWs;
    const float* r0b = g_r0 + (size_t)b * Cch * HWs;
    const int pidx = s_pidx;

    if (tid < 64) {
        s_ds[tid] = d0b[(size_t)tid * HWs + pidx];
        s_rs[tid] = r0b[(size_t)tid * HWs + pidx];
    }
    for (int i = tid; i < 64*Kn; i += 128) {
        int ch = i / Kn, k = i % Kn;
        s_dnn[ch][k] = d0b[(size_t)ch * HWs + s_nb[k]];
    }
    if (tid < 3*Kn) {
        int c3 = tid / Kn, k = tid % Kn;
        s_feat[k][128 + c3] = disp[(((size_t)b*3 + c3)*NS + n)*Kn + k];
    }
    __syncthreads();

    for (int i = tid; i < 64*Kn; i += 128) {
        int ch = i / Kn, k = i % Kn;
        float dn = s_dnn[ch][k];
        s_feat[k][ch]      = dn - s_ds[ch];
        s_feat[k][64 + ch] = dn - s_rs[ch];
    }
    __syncthreads();

    for (int t = tid; t < 2*Kn*Dhh; t += 128) {
        int m = t / (Kn*Dhh);
        int local = t % (Kn*Dhh);
        int k = local / Dhh;
        int j = local % Dhh;
        const float* W1 = m ? r_w1 : d_w1;
        float a = (m ? r_b1 : d_b1)[j];
#pragma unroll 1
        for (int d = 0; d < Dd; d++)
            a = fmaf(s_feat[k][d], __ldg(&W1[d*Dhh + j]), a);
        a = (a > 0.f) ? a : 0.2f * a;
        s_h[m][k][j] = a;
    }
    __syncthreads();

    if (tid < 2*Kn) {
        int m = tid / Kn, k = tid % Kn;
        const float* W2 = m ? r_w2 : d_w2;
        float a = (m ? r_b2 : d_b2)[0];
#pragma unroll 1
        for (int j = 0; j < Dhh; j++)
            a = fmaf(s_h[m][k][j], __ldg(&W2[j]), a);
        s_logit[m][k] = a;
    }
    __syncthreads();

    if (tid < 2) {
        int m = tid;
        float mx = s_logit[m][0];
#pragma unroll
        for (int k = 1; k < Kn; k++) mx = fmaxf(mx, s_logit[m][k]);
        float sum = 0.f;
        float e[Kn];
#pragma unroll
        for (int k = 0; k < Kn; k++) { e[k] = expf(s_logit[m][k] - mx); sum += e[k]; }
        float inv = 1.f / sum;
#pragma unroll
        for (int k = 0; k < Kn; k++) s_attn[m][k] = e[k] * inv;
    }
    __syncthreads();

    if (tid < 64) {
        int ch = tid;
        float a = d_bias[ch];
#pragma unroll
        for (int k = 0; k < Kn; k++) a = fmaf(s_attn[0][k], s_dnn[ch][k], a);
        g_dfeat[((size_t)b*Cch + ch)*NS + n] = a;
    } else if (tid < 128) {
        int ch = tid - 64;
        float a = r_bias[ch];
#pragma unroll
        for (int k = 0; k < Kn; k++) a = fmaf(s_attn[1][k], s_dnn[ch][k], a);
        g_rfeat[((size_t)b*Cch + ch)*NS + n] = a;
    }
}

// ---------------- scatter update (pc indices unique -> race-free) ----------
__global__ __launch_bounds__(128) void scatter_kernel(const int* __restrict__ pc)
{
    const int n = blockIdx.x;
    const int b = blockIdx.y;
    const int tid = threadIdx.x;
    const int idx = pc[(size_t)b*NS + n];

    if (tid < 64) {
        int ch = tid;
        float v = g_dfeat[((size_t)b*Cch + ch)*NS + n];
        size_t o = ((size_t)b*Cch + ch)*HWs + idx;
        g_d0[o] = (ch == 0) ? v : (g_d0[o] + v);
    } else {
        int ch = tid - 64;
        float v = g_rfeat[((size_t)b*Cch + ch)*NS + n];
        size_t o = ((size_t)b*Cch + ch)*HWs + idx;
        g_r0[o] = (ch == 0) ? v : (g_r0[o] + v);
    }
}

// ---------------------------------------------------------------------------
extern "C" void kernel_launch(void* const* d_in, const int* in_sizes, int n_in,
                              void* d_out, int out_size)
{
    const float* rgb    = (const float*)d_in[0];
    const float* sdepth = (const float*)d_in[1];
    const int*   pc     = (const int*)  d_in[2];
    const int*   nbrs   = (const int*)  d_in[3];
    const float* disp   = (const float*)d_in[4];
    const float* d_c0w  = (const float*)d_in[5];
    const float* d_c0b  = (const float*)d_in[6];
    const float* d_c1w  = (const float*)d_in[7];
    const float* d_c1b  = (const float*)d_in[8];
    const float* d_c2w  = (const float*)d_in[9];
    const float* d_c2b  = (const float*)d_in[10];
    const float* r_c0w  = (const float*)d_in[11];
    const float* r_c0b  = (const float*)d_in[12];
    const float* r_c1w  = (const float*)d_in[13];
    const float* r_c1b  = (const float*)d_in[14];
    const float* r_c2w  = (const float*)d_in[15];
    const float* r_c2b  = (const float*)d_in[16];
    const float* d_w1   = (const float*)d_in[17];
    const float* d_b1   = (const float*)d_in[18];
    const float* d_w2   = (const float*)d_in[19];
    const float* d_b2   = (const float*)d_in[20];
    const float* r_w1   = (const float*)d_in[21];
    const float* r_b1   = (const float*)d_in[22];
    const float* r_w2   = (const float*)d_in[23];
    const float* r_b2   = (const float*)d_in[24];
    const float* d_bias = (const float*)d_in[25];
    const float* r_bias = (const float*)d_in[26];
    float* out = (float*)d_out;

    float *p_gd0, *p_gr0;
    uint32_t* p_wf;
    cudaGetSymbolAddress((void**)&p_gd0, g_d0);
    cudaGetSymbolAddress((void**)&p_gr0, g_r0);
    cudaGetSymbolAddress((void**)&p_wf, g_wfrag);

    // weight prepack: sets 0:d0 1:r0 2:d2 3:d1 4:r2 5:r1
    prepack_w<<<dim3(288, 6), 32>>>(d_c0w, r_c0w, d_c2w, d_c1w, r_c2w, r_c1w);

    dim3 cgrid(Ww/16, Hh/8, Bsz);

    // Stage A
    conv3x3_mma<<<cgrid, 256>>>(sdepth, p_wf + 0*WSET_U32, nullptr, nullptr,
                                d_c0b, nullptr, p_gd0);
    conv3x3_mma<<<cgrid, 256>>>(rgb,    p_wf + 1*WSET_U32, nullptr, nullptr,
                                r_c0b, nullptr, p_gr0);

    // Stage B
    point_kernel<<<dim3(NS, Bsz), 128>>>(pc, nbrs, disp,
                                         d_w1, d_b1, d_w2, d_b2,
                                         r_w1, r_b1, r_w2, r_b2,
                                         d_bias, r_bias);
    scatter_kernel<<<dim3(NS, Bsz), 128>>>(pc);

    // Stage C (fused dual-source convs)
    conv3x3_mma<<<cgrid, 256>>>(p_gd0, p_wf + 2*WSET_U32, sdepth, p_wf + 3*WSET_U32,
                                d_c2b, d_c1b, out);
    conv3x3_mma<<<cgrid, 256>>>(p_gr0, p_wf + 4*WSET_U32, rgb, p_wf + 5*WSET_U32,
                                r_c2b, r_c1b, out + (size_t)Bsz*Cch*HWs);
}